// round 1
// baseline (speedup 1.0000x reference)
#include <cuda_runtime.h>
#include <cstdint>

#define BB   64
#define TT_  2000
#define AA   256
#define FF   32
#define KK   31
#define TILE 100
#define NTIL 20
#define WSZ  (TILE + 32)

// Scratch (no allocations allowed)
__device__ float g_W2[(KK + 1) * AA];   // rows 0..30: conv_w @ loc_w ; row 31: conv_b @ loc_w
__device__ float g_energy[BB * TT_];

// ---------------------------------------------------------------------------
// Fold conv_w (K,1,F) with loc_w (F,A):  W2[k,a] = sum_f cw[k,f]*lw[f,a]
// ---------------------------------------------------------------------------
__global__ void w2_kernel(const float* __restrict__ cw,
                          const float* __restrict__ cb,
                          const float* __restrict__ lw) {
    int a = threadIdx.x;
    #pragma unroll 1
    for (int k = 0; k < KK; ++k) {
        float s = 0.f;
        #pragma unroll
        for (int f = 0; f < FF; ++f) s = fmaf(cw[k * FF + f], lw[f * AA + a], s);
        g_W2[k * AA + a] = s;
    }
    float sb = 0.f;
    #pragma unroll
    for (int f = 0; f < FF; ++f) sb = fmaf(cb[f], lw[f * AA + a], sb);
    g_W2[KK * AA + a] = sb;
}

// ---------------------------------------------------------------------------
// Energy kernel: one block = (b, t-tile), 256 threads, thread = one 'a'.
// ploc via packed f32x2 FMA over prepacked even/odd pw pair arrays in smem.
// Tiles fully past memory_length exit immediately (softmax never reads them).
// ---------------------------------------------------------------------------
__global__ __launch_bounds__(256) void energy_kernel(
    const float* __restrict__ query,
    const float* __restrict__ pw,
    const float* __restrict__ wmem,
    const int*   __restrict__ lens,
    const float* __restrict__ sv,
    const float* __restrict__ sb) {

    __shared__ float Wf[WSZ];
    __shared__ unsigned long long Esh[WSZ / 2];
    __shared__ unsigned long long Osh[WSZ / 2];
    __shared__ float Wsum[8][TILE];

    const int b   = blockIdx.y;
    const int t0  = blockIdx.x * TILE;
    const int len = lens[b];
    if (t0 >= len) return;                       // fully-masked tile: skip all work
    const int n   = min(t0 + TILE, len) - t0;

    const int tid = threadIdx.x;
    const int a   = tid;

    // pw window: Wf[i] = pw[b, t0-15+i], zero-padded (SAME conv padding)
    for (int i = tid; i < WSZ; i += 256) {
        int g = t0 - 15 + i;
        Wf[i] = (g >= 0 && g < TT_) ? pw[b * TT_ + g] : 0.f;
    }
    __syncthreads();
    // Packed pair arrays: E[j]=(W[2j],W[2j+1]) low,high ; O[j]=(W[2j+1],W[2j+2])
    for (int j = tid; j < WSZ / 2; j += 256) {
        float w0 = Wf[2 * j], w1 = Wf[2 * j + 1];
        float w2v = (2 * j + 2 < WSZ) ? Wf[2 * j + 2] : 0.f;
        Esh[j] = ((unsigned long long)__float_as_uint(w1) << 32) | __float_as_uint(w0);
        Osh[j] = ((unsigned long long)__float_as_uint(w2v) << 32) | __float_as_uint(w1);
    }
    __syncthreads();

    // Per-thread constants (column 'a')
    const float qb  = query[b * AA + a] + sb[a] + g_W2[KK * AA + a];
    const float svv = sv[a];
    unsigned long long w2p[15];
    #pragma unroll
    for (int j = 0; j < 15; ++j) {
        unsigned lo = __float_as_uint(g_W2[(2 * j) * AA + a]);
        unsigned hi = __float_as_uint(g_W2[(2 * j + 1) * AA + a]);
        w2p[j] = ((unsigned long long)hi << 32) | lo;
    }
    const float w2last = g_W2[30 * AA + a];

    const float* xp = wmem + ((size_t)(b * TT_ + t0)) * AA + a;
    float xnext = __ldg(xp);

    for (int tt = 0; tt < n; ++tt) {
        float x = xnext;
        xp += AA;
        if (tt + 1 < n) xnext = __ldg(xp);       // prefetch next t

        // ploc(tt) = sum_{k=0..30} Wf[tt+k] * W2[k,a]
        const unsigned long long* bp = (tt & 1) ? (Osh + (tt >> 1)) : (Esh + (tt >> 1));
        unsigned long long acc = (unsigned long long)__float_as_uint(x + qb); // (x+qb, 0)
        #pragma unroll
        for (int j = 0; j < 15; ++j) {
            unsigned long long p = bp[j];
            asm("fma.rn.f32x2 %0, %1, %2, %0;" : "+l"(acc) : "l"(p), "l"(w2p[j]));
        }
        float lo  = __uint_as_float((unsigned)acc);
        float hi  = __uint_as_float((unsigned)(acc >> 32));
        float arg = fmaf(Wf[tt + 30], w2last, lo + hi);

        // tanh(x) = 1 - 2/(e^{2x}+1) ; ex2/rcp approx, err ~1e-6
        float u, r;
        asm("ex2.approx.f32 %0, %1;" : "=f"(u) : "f"(arg * 2.8853900817779268f));
        asm("rcp.approx.f32 %0, %1;" : "=f"(r) : "f"(u + 1.0f));
        float p = svv * fmaf(-2.0f, r, 1.0f);

        // reduce 256 -> 8 warp partials (no per-t barrier)
        p += __shfl_xor_sync(0xffffffffu, p, 16);
        p += __shfl_xor_sync(0xffffffffu, p, 8);
        p += __shfl_xor_sync(0xffffffffu, p, 4);
        p += __shfl_xor_sync(0xffffffffu, p, 2);
        p += __shfl_xor_sync(0xffffffffu, p, 1);
        if ((tid & 31) == 0) Wsum[tid >> 5][tt] = p;
    }
    __syncthreads();
    for (int i = tid; i < n; i += 256) {
        float s = 0.f;
        #pragma unroll
        for (int w = 0; w < 8; ++w) s += Wsum[w][i];
        g_energy[b * TT_ + t0 + i] = s;
    }
}

// ---------------------------------------------------------------------------
// Softmax per b over t < len; masked entries are exact 0 (== reference,
// since exp(MASK_VAL - max) flushes to 0 in fp32).
// out[0 .. B*T)       = alignments
// out[B*T .. 2*B*T)   = alignments + prev_weights
// ---------------------------------------------------------------------------
__global__ __launch_bounds__(256) void softmax_kernel(
    const float* __restrict__ pw,
    const int*   __restrict__ lens,
    float*       __restrict__ out) {

    __shared__ float red[8];
    __shared__ float s_m, s_inv;
    const int b = blockIdx.x, tid = threadIdx.x;
    const int len = lens[b];
    const float* e = g_energy + b * TT_;

    float m = -3.402823466e38f;
    for (int t = tid; t < len; t += 256) m = fmaxf(m, e[t]);
    #pragma unroll
    for (int o = 16; o; o >>= 1) m = fmaxf(m, __shfl_xor_sync(0xffffffffu, m, o));
    if ((tid & 31) == 0) red[tid >> 5] = m;
    __syncthreads();
    if (tid < 32) {
        float v = (tid < 8) ? red[tid] : -3.402823466e38f;
        #pragma unroll
        for (int o = 4; o; o >>= 1) v = fmaxf(v, __shfl_xor_sync(0xffffffffu, v, o));
        if (tid == 0) s_m = v;
    }
    __syncthreads();
    m = s_m;

    float s = 0.f;
    for (int t = tid; t < len; t += 256) s += __expf(e[t] - m);
    #pragma unroll
    for (int o = 16; o; o >>= 1) s += __shfl_xor_sync(0xffffffffu, s, o);
    if ((tid & 31) == 0) red[tid >> 5] = s;
    __syncthreads();
    if (tid < 32) {
        float v = (tid < 8) ? red[tid] : 0.f;
        #pragma unroll
        for (int o = 4; o; o >>= 1) v += __shfl_xor_sync(0xffffffffu, v, o);
        if (tid == 0) s_inv = 1.0f / v;
    }
    __syncthreads();
    const float inv = s_inv;

    for (int t = tid; t < TT_; t += 256) {
        float w = (t < len) ? __expf(e[t] - m) * inv : 0.f;
        out[b * TT_ + t] = w;
        out[BB * TT_ + b * TT_ + t] = w + pw[b * TT_ + t];
    }
}

// ---------------------------------------------------------------------------
extern "C" void kernel_launch(void* const* d_in, const int* in_sizes, int n_in,
                              void* d_out, int out_size) {
    const float* query  = (const float*)d_in[0];
    const float* prevw  = (const float*)d_in[1];
    const float* wmem   = (const float*)d_in[2];
    const int*   lens   = (const int*)  d_in[3];
    const float* convw  = (const float*)d_in[4];
    const float* convb  = (const float*)d_in[5];
    const float* locw   = (const float*)d_in[6];
    const float* scorev = (const float*)d_in[7];
    const float* scoreb = (const float*)d_in[8];
    float* out = (float*)d_out;

    w2_kernel<<<1, 256>>>(convw, convb, locw);
    energy_kernel<<<dim3(NTIL, BB), 256>>>(query, prevw, wmem, lens, scorev, scoreb);
    softmax_kernel<<<BB, 256>>>(prevw, lens, out);
}

// round 2
// speedup vs baseline: 1.7965x; 1.7965x over previous
#include <cuda_runtime.h>
#include <cstdint>

#define BB   64
#define TT_  2000
#define AA   256
#define FF   32
#define KK   31
#define TILE 100
#define NTIL 20
#define WFSZ 138          // pw window floats (need up to index 136)
#define NPR  68           // pair-array entries (need up to index 64)

typedef unsigned long long ull;

// Scratch (no allocations allowed)
__device__ float g_W2[(KK + 1) * AA];   // rows 0..30: conv_w @ loc_w ; row 31: conv_b @ loc_w
__device__ float g_energy[BB * TT_];

#define FMA2(acc, p, w) asm("fma.rn.f32x2 %0, %1, %2, %0;" : "+l"(acc) : "l"(p), "l"(w))

// ---------------------------------------------------------------------------
// W2[k,a] = sum_f cw[k,f]*lw[f,a]  (block = tap row k; row 31 = bias row)
// ---------------------------------------------------------------------------
__global__ __launch_bounds__(256) void w2_kernel(const float* __restrict__ cw,
                                                 const float* __restrict__ cb,
                                                 const float* __restrict__ lw) {
    const int k = blockIdx.x;            // 0..31
    const int a = threadIdx.x;
    __shared__ float c[FF];
    if (a < FF) c[a] = (k < KK) ? cw[k * FF + a] : cb[a];
    __syncthreads();
    float s = 0.f;
    #pragma unroll
    for (int f = 0; f < FF; ++f) s = fmaf(c[f], lw[f * AA + a], s);
    g_W2[k * AA + a] = s;
}

// ---------------------------------------------------------------------------
// Energy kernel: block = (b, t-tile), 256 threads, thread = one 'a' column.
// 4-way t-unroll; sliding LDS.128 over prepacked even/odd pw pair arrays.
// K padded to 32 taps (W2[31] = 0) so no scalar tail.
// ---------------------------------------------------------------------------
__global__ __launch_bounds__(256) void energy_kernel(
    const float* __restrict__ query,
    const float* __restrict__ pw,
    const float* __restrict__ wmem,
    const int*   __restrict__ lens,
    const float* __restrict__ sv,
    const float* __restrict__ sb) {

    __shared__ float Wf[WFSZ];
    __shared__ __align__(16) ull Esh[NPR];
    __shared__ __align__(16) ull Osh[NPR];
    __shared__ float Wsum[8][TILE];

    const int b   = blockIdx.y;
    const int t0  = blockIdx.x * TILE;
    const int len = lens[b];
    if (t0 >= len) return;                       // fully-masked tile: skip
    const int n   = min(t0 + TILE, len) - t0;
    const int n4  = (n + 3) & ~3;

    const int tid = threadIdx.x;
    const int a   = tid;

    // pw window: Wf[i] = pw[b, t0-15+i], zero-padded (SAME conv padding)
    for (int i = tid; i < WFSZ; i += 256) {
        int g = t0 - 15 + i;
        Wf[i] = (g >= 0 && g < TT_) ? pw[b * TT_ + g] : 0.f;
    }
    __syncthreads();
    // Pair arrays: Esh[m]=(Wf[2m],Wf[2m+1])  Osh[m]=(Wf[2m+1],Wf[2m+2])
    for (int j = tid; j < NPR; j += 256) {
        float w0 = Wf[2 * j], w1 = Wf[2 * j + 1];
        float wv = (2 * j + 2 < WFSZ) ? Wf[2 * j + 2] : 0.f;
        Esh[j] = ((ull)__float_as_uint(w1) << 32) | __float_as_uint(w0);
        Osh[j] = ((ull)__float_as_uint(wv) << 32) | __float_as_uint(w1);
    }
    __syncthreads();

    // Per-thread constants (column 'a')
    const float qb  = query[b * AA + a] + sb[a] + g_W2[KK * AA + a];
    const float svv = sv[a];
    const ull   qb0 = (ull)__float_as_uint(qb);   // (qb, 0.0f)
    ull w2p[16];
    #pragma unroll
    for (int j = 0; j < 15; ++j) {
        unsigned lo = __float_as_uint(g_W2[(2 * j) * AA + a]);
        unsigned hi = __float_as_uint(g_W2[(2 * j + 1) * AA + a]);
        w2p[j] = ((ull)hi << 32) | lo;
    }
    w2p[15] = (ull)__float_as_uint(g_W2[30 * AA + a]);   // (W2[30], 0)

    const float* xp = wmem + ((size_t)(b * TT_ + t0)) * AA + a;

    for (int tb = 0; tb < n4; tb += 4) {
        const int h = tb >> 1;                   // even -> 16B-aligned pair base
        // wmem loads (coalesced over a); guard OOB tail
        float x0 = (tb + 0 < n) ? __ldg(xp)          : 0.f;
        float x1 = (tb + 1 < n) ? __ldg(xp + AA)     : 0.f;
        float x2 = (tb + 2 < n) ? __ldg(xp + 2 * AA) : 0.f;
        float x3 = (tb + 3 < n) ? __ldg(xp + 3 * AA) : 0.f;
        xp += 4 * AA;

        ull a0 = qb0, a1 = qb0, a2 = qb0, a3 = qb0;
        const ulonglong2* Ep = (const ulonglong2*)(Esh + h);
        const ulonglong2* Op = (const ulonglong2*)(Osh + h);
        #pragma unroll
        for (int m = 0; m < 8; ++m) {
            ulonglong2 e = Ep[m];                // LDS.128 (broadcast)
            FMA2(a0, e.x, w2p[2 * m]);
            FMA2(a0, e.y, w2p[2 * m + 1]);
            if (m > 0) FMA2(a2, e.x, w2p[2 * m - 1]);
            FMA2(a2, e.y, w2p[2 * m]);
            ulonglong2 o = Op[m];
            FMA2(a1, o.x, w2p[2 * m]);
            FMA2(a1, o.y, w2p[2 * m + 1]);
            if (m > 0) FMA2(a3, o.x, w2p[2 * m - 1]);
            FMA2(a3, o.y, w2p[2 * m]);
        }
        { ull e16 = Esh[h + 16]; FMA2(a2, e16, w2p[15]); }
        { ull o16 = Osh[h + 16]; FMA2(a3, o16, w2p[15]); }

        float p[4];
        {
            float arg, u, r;
            #define FIN(acc, x, out)                                              \
                arg = __uint_as_float((unsigned)(acc)) +                          \
                      __uint_as_float((unsigned)((acc) >> 32)) + (x);             \
                asm("ex2.approx.f32 %0, %1;" : "=f"(u) : "f"(arg * 2.8853900817779268f)); \
                asm("rcp.approx.f32 %0, %1;" : "=f"(r) : "f"(u + 1.0f));          \
                out = svv * fmaf(-2.0f, r, 1.0f);
            FIN(a0, x0, p[0]); FIN(a1, x1, p[1]);
            FIN(a2, x2, p[2]); FIN(a3, x3, p[3]);
            #undef FIN
        }

        // 4 interleaved warp-reduction chains
        #pragma unroll
        for (int r = 0; r < 4; ++r) {
            float v = p[r];
            v += __shfl_xor_sync(0xffffffffu, v, 16);
            v += __shfl_xor_sync(0xffffffffu, v, 8);
            v += __shfl_xor_sync(0xffffffffu, v, 4);
            v += __shfl_xor_sync(0xffffffffu, v, 2);
            v += __shfl_xor_sync(0xffffffffu, v, 1);
            p[r] = v;
        }
        if ((tid & 31) == 0) {
            Wsum[tid >> 5][tb + 0] = p[0];
            Wsum[tid >> 5][tb + 1] = p[1];
            Wsum[tid >> 5][tb + 2] = p[2];
            Wsum[tid >> 5][tb + 3] = p[3];
        }
    }
    __syncthreads();
    for (int i = tid; i < n; i += 256) {
        float s = 0.f;
        #pragma unroll
        for (int w = 0; w < 8; ++w) s += Wsum[w][i];
        g_energy[b * TT_ + t0 + i] = s;
    }
}

// ---------------------------------------------------------------------------
// Softmax per b over t < len; masked entries exact 0 (matches reference:
// exp(MASK_VAL - max) flushes to 0 in fp32).
// ---------------------------------------------------------------------------
__global__ __launch_bounds__(256) void softmax_kernel(
    const float* __restrict__ pw,
    const int*   __restrict__ lens,
    float*       __restrict__ out) {

    __shared__ float red[8];
    __shared__ float s_m, s_inv;
    const int b = blockIdx.x, tid = threadIdx.x;
    const int len = lens[b];
    const float* e = g_energy + b * TT_;

    float m = -3.402823466e38f;
    for (int t = tid; t < len; t += 256) m = fmaxf(m, e[t]);
    #pragma unroll
    for (int o = 16; o; o >>= 1) m = fmaxf(m, __shfl_xor_sync(0xffffffffu, m, o));
    if ((tid & 31) == 0) red[tid >> 5] = m;
    __syncthreads();
    if (tid < 32) {
        float v = (tid < 8) ? red[tid] : -3.402823466e38f;
        #pragma unroll
        for (int o = 4; o; o >>= 1) v = fmaxf(v, __shfl_xor_sync(0xffffffffu, v, o));
        if (tid == 0) s_m = v;
    }
    __syncthreads();
    m = s_m;

    float s = 0.f;
    for (int t = tid; t < len; t += 256) s += __expf(e[t] - m);
    #pragma unroll
    for (int o = 16; o; o >>= 1) s += __shfl_xor_sync(0xffffffffu, s, o);
    if ((tid & 31) == 0) red[tid >> 5] = s;
    __syncthreads();
    if (tid < 32) {
        float v = (tid < 8) ? red[tid] : 0.f;
        #pragma unroll
        for (int o = 4; o; o >>= 1) v += __shfl_xor_sync(0xffffffffu, v, o);
        if (tid == 0) s_inv = 1.0f / v;
    }
    __syncthreads();
    const float inv = s_inv;

    for (int t = tid; t < TT_; t += 256) {
        float w = (t < len) ? __expf(e[t] - m) * inv : 0.f;
        out[b * TT_ + t] = w;
        out[BB * TT_ + b * TT_ + t] = w + pw[b * TT_ + t];
    }
}

// ---------------------------------------------------------------------------
extern "C" void kernel_launch(void* const* d_in, const int* in_sizes, int n_in,
                              void* d_out, int out_size) {
    const float* query  = (const float*)d_in[0];
    const float* prevw  = (const float*)d_in[1];
    const float* wmem   = (const float*)d_in[2];
    const int*   lens   = (const int*)  d_in[3];
    const float* convw  = (const float*)d_in[4];
    const float* convb  = (const float*)d_in[5];
    const float* locw   = (const float*)d_in[6];
    const float* scorev = (const float*)d_in[7];
    const float* scoreb = (const float*)d_in[8];
    float* out = (float*)d_out;

    w2_kernel<<<KK + 1, 256>>>(convw, convb, locw);
    energy_kernel<<<dim3(NTIL, BB), 256>>>(query, prevw, wmem, lens, scorev, scoreb);
    softmax_kernel<<<BB, 256>>>(prevw, lens, out);
}